// round 13
// baseline (speedup 1.0000x reference)
#include <cuda_runtime.h>

// ICLoss: negative soft-rank information coefficient.
//   r_i = sum_j sigmoid(x_i - x_j) + 1
// Using u = exp(x):  sigmoid(x_i - x_j) = u_i / (u_i + u_j)
//   => r_i = u_i * sum_j 1/(ui + uj) + 1
//
// Inner loop: group-of-8 polynomial trick, TWO groups at a time via packed
// fp32x2 FMA (PTX fma.rn.f32x2 -> SASS FFMA2).
//   Q(x) = prod_{j in G} (x + u_j);  sum_{j in G} 1/(ui+u_j) = Q'(ui)/Q(ui)
//
// Round-13: the entire O(N) epilogue is fused into rank_kernel via a
// hierarchical "last block done" pattern (no second launch):
//   - per row-set rb: 32 producer blocks (16 j-splits x 2 matrices); the last
//     to arrive (atomicInc, self-wrapping) assembles ranks + fp64 moments for
//     its 256 rows -> g_stats[rb]. Runs overlapped with remaining rank work.
//   - the last of the 32 rb-finishers combines g_stats in fixed order -> -ic.
// All reductions are fixed-order => bit-deterministic across graph replays.

#define NN 8192
#define JSPLIT 16
#define CHUNK 512               // NN / JSPLIT
#define GSIZE 8                 // j's per polynomial group
#define GROUPS (CHUNK / GSIZE)  // 64 groups per chunk
#define PAIRS (GROUPS / 2)      // 32 group-pairs per chunk
#define ROWS 256                // rows per block
#define ROWBLKS 32              // NN / ROWS

// Scratch (no device allocation allowed -> __device__ globals).
__device__ float  g_part[2][NN][JSPLIT];
__device__ double g_stats[ROWBLKS][5];
__device__ unsigned int g_cnt[ROWBLKS];   // 32 arrivals each, self-wrapping
__device__ unsigned int g_done;           // 32 arrivals, self-wrapping

__device__ __forceinline__ unsigned long long fma2(unsigned long long a,
                                                   unsigned long long b,
                                                   unsigned long long c) {
    unsigned long long d;
    asm("fma.rn.f32x2 %0, %1, %2, %3;" : "=l"(d) : "l"(a), "l"(b), "l"(c));
    return d;
}
__device__ __forceinline__ unsigned long long add2(unsigned long long a,
                                                   unsigned long long b) {
    unsigned long long d;
    asm("add.rn.f32x2 %0, %1, %2;" : "=l"(d) : "l"(a), "l"(b));
    return d;
}

__global__ void __launch_bounds__(256) rank_kernel(const float* __restrict__ pred,
                                                   const float* __restrict__ targ,
                                                   float* __restrict__ out) {
    // Interleaved coeff pairs: float index p*16 + j*2 + half = e_{j+1} of
    // group 2p+half. ulonglong2 view packs (eA|eB) register pairs.
    __shared__ ulonglong2 sc[PAIRS * 4];
    __shared__ double red[5][8];
    __shared__ unsigned int sTicket;

    const int b   = blockIdx.x;
    const int js  = b & (JSPLIT - 1);        // which 512-column chunk
    const int rb  = (b >> 4) & (ROWBLKS - 1);// which 256-row block
    const int m   = b >> 9;                  // 0 = predictions, 1 = targets
    const int tid = threadIdx.x;
    const int lane = tid & 31;
    const int w    = tid >> 5;

    const float* __restrict__ x = m ? targ : pred;

    // Setup: threads 0..63 each expand one group's monic polynomial coeffs.
    if (tid < GROUPS) {
        const float4* gx = reinterpret_cast<const float4*>(x + js * CHUNK + tid * GSIZE);
        float4 x0 = gx[0], x1 = gx[1];
        float u[GSIZE] = { __expf(x0.x), __expf(x0.y), __expf(x0.z), __expf(x0.w),
                           __expf(x1.x), __expf(x1.y), __expf(x1.z), __expf(x1.w) };
        float c[GSIZE + 1];
        c[0] = 1.0f;
#pragma unroll
        for (int k = 1; k <= GSIZE; ++k) c[k] = 0.0f;
#pragma unroll
        for (int l = 0; l < GSIZE; ++l) {
#pragma unroll
            for (int k = GSIZE; k >= 1; --k)
                c[k] = __fmaf_rn(u[l], c[k - 1], c[k]);
        }
        float* scf = reinterpret_cast<float*>(sc);
        const int p = tid >> 1, half = tid & 1;
#pragma unroll
        for (int j = 0; j < GSIZE; ++j)
            scf[p * 16 + j * 2 + half] = c[j + 1];
    }

    const int   i  = rb * ROWS + tid;
    const float ui = __expf(x[i]);
    __syncthreads();

    unsigned long long ui2;
    {
        unsigned int uib = __float_as_uint(ui);
        asm("mov.b64 %0, {%1, %1};" : "=l"(ui2) : "r"(uib));
    }

    // acc = sum over chunk of 1/(ui + uj), two groups of 8 per iteration.
    float acc = 0.0f;
#pragma unroll 4
    for (int p = 0; p < PAIRS; ++p) {
        ulonglong2 v0 = sc[p * 4 + 0];   // e1|e2 pairs
        ulonglong2 v1 = sc[p * 4 + 1];   // e3|e4
        ulonglong2 v2 = sc[p * 4 + 2];   // e5|e6
        ulonglong2 v3 = sc[p * 4 + 3];   // e7|e8

        unsigned long long q, qp;
        q  = add2(ui2, v0.x);            // q = x + e1 (both groups)
        qp = add2(ui2, q);               // qp = x + q
        q  = fma2(q, ui2, v0.y);         // e2
        qp = fma2(qp, ui2, q);  q = fma2(q, ui2, v1.x);   // e3
        qp = fma2(qp, ui2, q);  q = fma2(q, ui2, v1.y);   // e4
        qp = fma2(qp, ui2, q);  q = fma2(q, ui2, v2.x);   // e5
        qp = fma2(qp, ui2, q);  q = fma2(q, ui2, v2.y);   // e6
        qp = fma2(qp, ui2, q);  q = fma2(q, ui2, v3.x);   // e7
        qp = fma2(qp, ui2, q);  q = fma2(q, ui2, v3.y);   // e8

        unsigned int qa, qb, qpa, qpb;
        asm("mov.b64 {%0, %1}, %2;" : "=r"(qa),  "=r"(qb)  : "l"(q));
        asm("mov.b64 {%0, %1}, %2;" : "=r"(qpa), "=r"(qpb) : "l"(qp));
        float qA  = __uint_as_float(qa),  qB  = __uint_as_float(qb);
        float qpA = __uint_as_float(qpa), qpB = __uint_as_float(qpb);

        float den = qA * qB;
        float num = __fmaf_rn(qpA, qB, qpB * qA);
        float r;
        asm("rcp.approx.f32 %0, %1;" : "=f"(r) : "f"(den));
        acc = __fmaf_rn(num, r, acc);    // += Q'A/QA + Q'B/QB
    }

    g_part[m][i][js] = ui * acc;         // partial of sum_j sigmoid(x_i - x_j)

    // ---- fused epilogue, level 1: last of the 32 producers for this rb ----
    __threadfence();
    __syncthreads();
    if (tid == 0)
        sTicket = atomicInc(&g_cnt[rb], 2 * JSPLIT - 1);   // wraps to 0 -> replay-safe
    __syncthreads();
    if (sTicket != 2 * JSPLIT - 1) return;

    // This block is the finisher for row-set rb: assemble ranks + moments.
    {
        const int r = rb * ROWS + tid;
        const float4* pp = reinterpret_cast<const float4*>(g_part[0][r]);
        const float4* tp = reinterpret_cast<const float4*>(g_part[1][r]);
        float4 a0 = __ldcg(pp + 0), a1 = __ldcg(pp + 1);
        float4 a2 = __ldcg(pp + 2), a3 = __ldcg(pp + 3);
        float4 c0 = __ldcg(tp + 0), c1 = __ldcg(tp + 1);
        float4 c2 = __ldcg(tp + 2), c3 = __ldcg(tp + 3);

        float rp = 1.0f + ((a0.x + a0.y) + (a0.z + a0.w))
                        + ((a1.x + a1.y) + (a1.z + a1.w))
                        + ((a2.x + a2.y) + (a2.z + a2.w))
                        + ((a3.x + a3.y) + (a3.z + a3.w));
        float rt = 1.0f + ((c0.x + c0.y) + (c0.z + c0.w))
                        + ((c1.x + c1.y) + (c1.z + c1.w))
                        + ((c2.x + c2.y) + (c2.z + c2.w))
                        + ((c3.x + c3.y) + (c3.z + c3.w));

        double dp = (double)rp, dt = (double)rt;
        double sp  = dp,      st  = dt;
        double spp = dp * dp, stt = dt * dt, spt = dp * dt;

#pragma unroll
        for (int o = 16; o > 0; o >>= 1) {
            sp  += __shfl_down_sync(0xffffffffu, sp,  o);
            st  += __shfl_down_sync(0xffffffffu, st,  o);
            spp += __shfl_down_sync(0xffffffffu, spp, o);
            stt += __shfl_down_sync(0xffffffffu, stt, o);
            spt += __shfl_down_sync(0xffffffffu, spt, o);
        }
        if (lane == 0) {
            red[0][w] = sp;  red[1][w] = st;
            red[2][w] = spp; red[3][w] = stt; red[4][w] = spt;
        }
        __syncthreads();

        if (tid == 0) {
            double s0 = 0, s1 = 0, s2 = 0, s3 = 0, s4 = 0;
#pragma unroll
            for (int k = 0; k < 8; ++k) {
                s0 += red[0][k]; s1 += red[1][k]; s2 += red[2][k];
                s3 += red[3][k]; s4 += red[4][k];
            }
            g_stats[rb][0] = s0;
            g_stats[rb][1] = s1;
            g_stats[rb][2] = s2;
            g_stats[rb][3] = s3;
            g_stats[rb][4] = s4;
            __threadfence();
            sTicket = atomicInc(&g_done, ROWBLKS - 1);     // wraps -> replay-safe
        }
        __syncthreads();
    }

    // ---- fused epilogue, level 2: last rb-finisher combines and writes ----
    if (sTicket == ROWBLKS - 1 && w == 0) {
        double sp  = __ldcg(&g_stats[lane][0]);
        double st  = __ldcg(&g_stats[lane][1]);
        double spp = __ldcg(&g_stats[lane][2]);
        double stt = __ldcg(&g_stats[lane][3]);
        double spt = __ldcg(&g_stats[lane][4]);
#pragma unroll
        for (int o = 16; o > 0; o >>= 1) {
            sp  += __shfl_down_sync(0xffffffffu, sp,  o);
            st  += __shfl_down_sync(0xffffffffu, st,  o);
            spp += __shfl_down_sync(0xffffffffu, spp, o);
            stt += __shfl_down_sync(0xffffffffu, stt, o);
            spt += __shfl_down_sync(0xffffffffu, spt, o);
        }
        if (lane == 0) {
            const double n  = (double)NN;
            const double mp = sp / n;
            const double mt = st / n;
            double num = spt - n * mp * mt;          // sum(p_c * t_c)
            double dpp = spp - n * mp * mp;          // sum(p_c^2)
            double dtt = stt - n * mt * mt;          // sum(t_c^2)
            double ic  = num / (sqrt(dpp * dtt) + 1e-8);
            out[0] = (float)(-ic);
        }
    }
}

extern "C" void kernel_launch(void* const* d_in, const int* in_sizes, int n_in,
                              void* d_out, int out_size) {
    const float* pred = (const float*)d_in[0];
    const float* targ = (const float*)d_in[1];

    // Single launch: 2 matrices * 32 row-blocks * 16 j-splits = 1024 blocks.
    rank_kernel<<<2 * ROWBLKS * JSPLIT, 256>>>(pred, targ, (float*)d_out);
}